// round 9
// baseline (speedup 1.0000x reference)
#include <cuda_runtime.h>

typedef unsigned long long ull;

// Chain state: 4-channel fields only. h1 ping-pong, h2 stored per block.
__device__ float g_h1[2][16][4][64][64];   //  2.1 MB
__device__ float g_h2[32][16][4][64][64];  // 33.6 MB

// ---- packed fp32x2 helpers --------------------------------------------------
__device__ __forceinline__ ull ffma2(ull a, ull b, ull c) {
    ull d; asm("fma.rn.f32x2 %0, %1, %2, %3;" : "=l"(d) : "l"(a), "l"(b), "l"(c)); return d;
}
__device__ __forceinline__ ull fadd2(ull a, ull b) {
    ull d; asm("add.rn.f32x2 %0, %1, %2;" : "=l"(d) : "l"(a), "l"(b)); return d;
}
__device__ __forceinline__ ull pack2(float lo, float hi) {
    ull d; asm("mov.b64 %0, {%1, %2};" : "=l"(d) : "f"(lo), "f"(hi)); return d;
}
__device__ __forceinline__ ull dup2(float v) { return pack2(v, v); }
__device__ __forceinline__ ull relu2(ull z) {
    float lo, hi; asm("mov.b64 {%0, %1}, %2;" : "=f"(lo), "=f"(hi) : "l"(z));
    return pack2(fmaxf(lo, 0.f), fmaxf(hi, 0.f));
}
__device__ __forceinline__ ull packmid(ull a, ull b) {
    float alo, ahi, blo, bhi;
    asm("mov.b64 {%0, %1}, %2;" : "=f"(alo), "=f"(ahi) : "l"(a));
    asm("mov.b64 {%0, %1}, %2;" : "=f"(blo), "=f"(bhi) : "l"(b));
    return pack2(ahi, blo);
}

// ---------------------------------------------------------------------------
// k0: h1_0 = relu(W1_0 @ x + b1_0).  Memory-bound (reads x, 67MB).
// ---------------------------------------------------------------------------
__global__ __launch_bounds__(256) void k0_kernel(const float* __restrict__ x,
                                                 const float* __restrict__ w1,
                                                 const float* __restrict__ b1) {
    __shared__ float4 sW1T[256];
    __shared__ float  sB1[4];
    int tid = threadIdx.x;
    if (tid < 4) sB1[tid] = b1[tid];
    sW1T[tid] = make_float4(w1[tid], w1[256 + tid], w1[512 + tid], w1[768 + tid]);
    __syncthreads();

    int n  = blockIdx.x >> 4;
    int yg = blockIdx.x & 15;
    int px = tid & 63;
    int y  = yg * 4 + (tid >> 6);

    const float* xp = x + (size_t)n * 256 * 4096 + y * 64 + px;
    float a0 = sB1[0], a1 = sB1[1], a2 = sB1[2], a3 = sB1[3];
#pragma unroll 8
    for (int c = 0; c < 256; c++) {
        float  xv = xp[c * 4096];
        float4 w  = sW1T[c];
        a0 = fmaf(xv, w.x, a0);
        a1 = fmaf(xv, w.y, a1);
        a2 = fmaf(xv, w.z, a2);
        a3 = fmaf(xv, w.w, a3);
    }
    float* hp = &g_h1[0][n][0][y][px];
    hp[0]     = fmaxf(a0, 0.f);
    hp[4096]  = fmaxf(a1, 0.f);
    hp[8192]  = fmaxf(a2, 0.f);
    hp[12288] = fmaxf(a3, 0.f);
}

// ---------------------------------------------------------------------------
// chain_kernel (block i): R8 structure + depth-1 software-pipelined weight
// loads in the fused loop (rotated register double-buffer).
// ---------------------------------------------------------------------------
__global__ __launch_bounds__(256, 2) void chain_kernel(
    const float* __restrict__ w1, const float* __restrict__ b1,
    const float* __restrict__ w2, const float* __restrict__ b2,
    const float* __restrict__ w3, const float* __restrict__ b3,
    int blk)
{
    __shared__ __align__(16) float s_h1[4][18][18];
    __shared__ ull        s_w2d[144];        // dup-packed [j][k][dy][dx]
    __shared__ float      s_b2[4];
    __shared__ ulonglong2 s_wall[256][4];    // [c]: {w3.xy, w3.zw, w1.01, w1.23} dup-packed
    __shared__ ulonglong2 s_b3p[128];        // [c/2]: {dup b3[2c], dup b3[2c+1]}
    __shared__ float      s_b1n[4];
    __shared__ ull        s_cp[4][4][128];   // conv partials [q][j][pair]
    __shared__ ull        s_part[3][4][128]; // fused partials [q-1][j][pair]

    int tid  = threadIdx.x;
    int dual = tid & 63;          // 0..63
    int q    = tid >> 6;          // 0..3
    int n    = blockIdx.x >> 4;
    int tile = blockIdx.x & 15;
    int ty0  = (tile >> 2) * 16;
    int tx0  = (tile & 3)  * 16;

    int pA = dual;                // rows 0..7
    int pB = dual + 64;           // rows 8..15

    // weight staging (256 threads, c == tid)
    if (tid < 144) s_w2d[tid] = dup2(w2[blk * 144 + tid]);
    else if (tid < 148) s_b2[tid - 144] = b2[blk * 4 + (tid - 144)];
    if (blk < 31) {
        const float* w1n = w1 + (blk + 1) * 1024;
        int c = tid;
        float4 wr = *(const float4*)&w3[(blk * 256 + c) * 4];
        s_wall[c][0] = make_ulonglong2(dup2(wr.x), dup2(wr.y));
        s_wall[c][1] = make_ulonglong2(dup2(wr.z), dup2(wr.w));
        s_wall[c][2] = make_ulonglong2(dup2(w1n[c]),       dup2(w1n[256 + c]));
        s_wall[c][3] = make_ulonglong2(dup2(w1n[512 + c]), dup2(w1n[768 + c]));
        if ((c & 1) == 0)
            s_b3p[c >> 1] = make_ulonglong2(dup2(b3[blk * 256 + c]),
                                            dup2(b3[blk * 256 + c + 1]));
        if (tid >= 148 && tid < 152) s_b1n[tid - 148] = b1[(blk + 1) * 4 + (tid - 148)];
    }

    // halo tile load: 18x18x4 (zero pad = SAME padding)
    const float* h1base = &g_h1[blk & 1][n][0][0][0];
    for (int idx = tid; idx < 324; idx += 256) {
        int yy = idx / 18, xx = idx % 18;
        int gy = ty0 + yy - 1, gx = tx0 + xx - 1;
        bool ok = (gy >= 0 && gy < 64 && gx >= 0 && gx < 64);
#pragma unroll
        for (int k = 0; k < 4; k++)
            s_h1[k][yy][xx] = ok ? h1base[k * 4096 + gy * 64 + gx] : 0.f;
    }
    __syncthreads();

    // ---- conv3x3, input-channel k=q, for both pairs of this thread ----
#pragma unroll
    for (int s = 0; s < 2; s++) {
        int pair = s ? pB : pA;
        int py = pair >> 3;
        int x0 = (pair & 7) * 2;
        ull p0 = (q == 0) ? dup2(s_b2[0]) : 0ull;
        ull p1 = (q == 0) ? dup2(s_b2[1]) : 0ull;
        ull p2 = (q == 0) ? dup2(s_b2[2]) : 0ull;
        ull p3 = (q == 0) ? dup2(s_b2[3]) : 0ull;
#pragma unroll
        for (int dy = 0; dy < 3; dy++) {
            const ull* rowp = (const ull*)&s_h1[q][py + dy][x0];
            ull p01 = rowp[0], p23 = rowp[1];
            ull tap0 = p01, tap1 = packmid(p01, p23), tap2 = p23;
            int wi = q * 9 + dy * 3;
            p0 = ffma2(tap0, s_w2d[wi + 0], p0);
            p1 = ffma2(tap0, s_w2d[36 + wi + 0], p1);
            p2 = ffma2(tap0, s_w2d[72 + wi + 0], p2);
            p3 = ffma2(tap0, s_w2d[108 + wi + 0], p3);
            p0 = ffma2(tap1, s_w2d[wi + 1], p0);
            p1 = ffma2(tap1, s_w2d[36 + wi + 1], p1);
            p2 = ffma2(tap1, s_w2d[72 + wi + 1], p2);
            p3 = ffma2(tap1, s_w2d[108 + wi + 1], p3);
            p0 = ffma2(tap2, s_w2d[wi + 2], p0);
            p1 = ffma2(tap2, s_w2d[36 + wi + 2], p1);
            p2 = ffma2(tap2, s_w2d[72 + wi + 2], p2);
            p3 = ffma2(tap2, s_w2d[108 + wi + 2], p3);
        }
        s_cp[q][0][pair] = p0;
        s_cp[q][1][pair] = p1;
        s_cp[q][2][pair] = p2;
        s_cp[q][3][pair] = p3;
    }
    __syncthreads();

    ull uA0 = relu2(fadd2(fadd2(s_cp[0][0][pA], s_cp[1][0][pA]), fadd2(s_cp[2][0][pA], s_cp[3][0][pA])));
    ull uA1 = relu2(fadd2(fadd2(s_cp[0][1][pA], s_cp[1][1][pA]), fadd2(s_cp[2][1][pA], s_cp[3][1][pA])));
    ull uA2 = relu2(fadd2(fadd2(s_cp[0][2][pA], s_cp[1][2][pA]), fadd2(s_cp[2][2][pA], s_cp[3][2][pA])));
    ull uA3 = relu2(fadd2(fadd2(s_cp[0][3][pA], s_cp[1][3][pA]), fadd2(s_cp[2][3][pA], s_cp[3][3][pA])));
    ull uB0 = relu2(fadd2(fadd2(s_cp[0][0][pB], s_cp[1][0][pB]), fadd2(s_cp[2][0][pB], s_cp[3][0][pB])));
    ull uB1 = relu2(fadd2(fadd2(s_cp[0][1][pB], s_cp[1][1][pB]), fadd2(s_cp[2][1][pB], s_cp[3][1][pB])));
    ull uB2 = relu2(fadd2(fadd2(s_cp[0][2][pB], s_cp[1][2][pB]), fadd2(s_cp[2][2][pB], s_cp[3][2][pB])));
    ull uB3 = relu2(fadd2(fadd2(s_cp[0][3][pB], s_cp[1][3][pB]), fadd2(s_cp[2][3][pB], s_cp[3][3][pB])));

    int gyA = ty0 + (pA >> 3), gxA = tx0 + (pA & 7) * 2;
    int gyB = ty0 + (pB >> 3), gxB = tx0 + (pB & 7) * 2;
    if (q == 0) {
        ull* hA = (ull*)&g_h2[blk][n][0][gyA][gxA];
        hA[0] = uA0; hA[2048] = uA1; hA[4096] = uA2; hA[6144] = uA3;
        ull* hB = (ull*)&g_h2[blk][n][0][gyB][gxB];
        hB[0] = uB0; hB[2048] = uB1; hB[4096] = uB2; hB[6144] = uB3;
    }

    if (blk < 31) {
        ull aA0, aA1, aA2, aA3, aB0, aB1, aB2, aB3;
        if (q == 0) {
            aA0 = dup2(s_b1n[0]); aA1 = dup2(s_b1n[1]); aA2 = dup2(s_b1n[2]); aA3 = dup2(s_b1n[3]);
            aB0 = aA0; aB1 = aA1; aB2 = aA2; aB3 = aA3;
        } else {
            aA0 = aA1 = aA2 = aA3 = 0ull;
            aB0 = aB1 = aB2 = aB3 = 0ull;
        }
        int c0 = q << 6;

        // ---- software-pipelined fused loop: prefetch weights for cc+1 ----
        ulonglong2 wA = s_wall[c0][0], wB = s_wall[c0][1];
        ulonglong2 qA = s_wall[c0][2], qB = s_wall[c0][3];
        ulonglong2 bbp = s_b3p[c0 >> 1];
#pragma unroll 8
        for (int cc = 0; cc < 64; cc++) {
            int c = c0 + cc;
            // prefetch next iteration's weights (dead in last iter; ptxas prunes)
            ulonglong2 nwA, nwB, nqA, nqB, nbbp;
            if (cc < 63) {
                const ulonglong2* np = s_wall[c + 1];
                nwA = np[0]; nwB = np[1]; nqA = np[2]; nqB = np[3];
                if ((cc & 1) == 1) nbbp = s_b3p[(c + 1) >> 1];
                else               nbbp = bbp;
            } else {
                nwA = wA; nwB = wB; nqA = qA; nqB = qB; nbbp = bbp;
            }
            ull bb = (cc & 1) ? bbp.y : bbp.x;
            // pair A
            ull zA = ffma2(uA0, wA.x, bb);
            zA = ffma2(uA1, wA.y, zA);
            zA = ffma2(uA2, wB.x, zA);
            zA = ffma2(uA3, wB.y, zA);
            ull vA = relu2(zA);
            aA0 = ffma2(vA, qA.x, aA0);
            aA1 = ffma2(vA, qA.y, aA1);
            aA2 = ffma2(vA, qB.x, aA2);
            aA3 = ffma2(vA, qB.y, aA3);
            // pair B (independent chain — ILP)
            ull zB = ffma2(uB0, wA.x, bb);
            zB = ffma2(uB1, wA.y, zB);
            zB = ffma2(uB2, wB.x, zB);
            zB = ffma2(uB3, wB.y, zB);
            ull vB = relu2(zB);
            aB0 = ffma2(vB, qA.x, aB0);
            aB1 = ffma2(vB, qA.y, aB1);
            aB2 = ffma2(vB, qB.x, aB2);
            aB3 = ffma2(vB, qB.y, aB3);
            // rotate
            wA = nwA; wB = nwB; qA = nqA; qB = nqB; bbp = nbbp;
        }

        if (q > 0) {
            s_part[q - 1][0][pA] = aA0; s_part[q - 1][1][pA] = aA1;
            s_part[q - 1][2][pA] = aA2; s_part[q - 1][3][pA] = aA3;
            s_part[q - 1][0][pB] = aB0; s_part[q - 1][1][pB] = aB1;
            s_part[q - 1][2][pB] = aB2; s_part[q - 1][3][pB] = aB3;
        }
        __syncthreads();
        if (q == 0) {
            aA0 = fadd2(fadd2(aA0, s_part[0][0][pA]), fadd2(s_part[1][0][pA], s_part[2][0][pA]));
            aA1 = fadd2(fadd2(aA1, s_part[0][1][pA]), fadd2(s_part[1][1][pA], s_part[2][1][pA]));
            aA2 = fadd2(fadd2(aA2, s_part[0][2][pA]), fadd2(s_part[1][2][pA], s_part[2][2][pA]));
            aA3 = fadd2(fadd2(aA3, s_part[0][3][pA]), fadd2(s_part[1][3][pA], s_part[2][3][pA]));
            ull* hp = (ull*)&g_h1[(blk + 1) & 1][n][0][gyA][gxA];
            hp[0]    = relu2(aA0);
            hp[2048] = relu2(aA1);
            hp[4096] = relu2(aA2);
            hp[6144] = relu2(aA3);
            aB0 = fadd2(fadd2(aB0, s_part[0][0][pB]), fadd2(s_part[1][0][pB], s_part[2][0][pB]));
            aB1 = fadd2(fadd2(aB1, s_part[0][1][pB]), fadd2(s_part[1][1][pB], s_part[2][1][pB]));
            aB2 = fadd2(fadd2(aB2, s_part[0][2][pB]), fadd2(s_part[1][2][pB], s_part[2][2][pB]));
            aB3 = fadd2(fadd2(aB3, s_part[0][3][pB]), fadd2(s_part[1][3][pB], s_part[2][3][pB]));
            ull* hq = (ull*)&g_h1[(blk + 1) & 1][n][0][gyB][gxB];
            hq[0]    = relu2(aB0);
            hq[2048] = relu2(aB1);
            hq[4096] = relu2(aB2);
            hq[6144] = relu2(aB3);
        }
    }
}

// ---------------------------------------------------------------------------
// acc_kernel: out = sum_i relu(W3_i @ h2_i + b3_i)  (R6 form + pipelined loads)
// Grid 1024 (16 img x 64 rows), 256 threads = 16 dual-slots x 16 ch-groups.
// ---------------------------------------------------------------------------
__global__ __launch_bounds__(256) void acc_kernel(const float* __restrict__ w3,
                                                  const float* __restrict__ b3,
                                                  float* __restrict__ out) {
    __shared__ ulonglong2 s_w3d[256][2];
    __shared__ ull        s_b3d[256];
    __shared__ __align__(16) float s_u[4][64];

    int tid   = threadIdx.x;
    int n     = blockIdx.x >> 6;
    int y     = blockIdx.x & 63;
    int dual  = tid & 15;
    int grp   = tid >> 4;
    int pxA   = dual * 2;
    int pxB   = pxA + 32;
    int cbase = grp * 16;

    ull accA[16], accB[16];
#pragma unroll
    for (int cc = 0; cc < 16; cc++) { accA[cc] = 0ull; accB[cc] = 0ull; }

    for (int i = 0; i < 32; i++) {
        __syncthreads();
        float4 wr = *(const float4*)&w3[(i * 256 + tid) * 4];
        s_w3d[tid][0] = make_ulonglong2(dup2(wr.x), dup2(wr.y));
        s_w3d[tid][1] = make_ulonglong2(dup2(wr.z), dup2(wr.w));
        s_b3d[tid]    = dup2(b3[i * 256 + tid]);
        s_u[tid >> 6][tid & 63] = g_h2[i][n][tid >> 6][y][tid & 63];
        __syncthreads();

        ull uA0 = *(const ull*)&s_u[0][pxA];
        ull uA1 = *(const ull*)&s_u[1][pxA];
        ull uA2 = *(const ull*)&s_u[2][pxA];
        ull uA3 = *(const ull*)&s_u[3][pxA];
        ull uB0 = *(const ull*)&s_u[0][pxB];
        ull uB1 = *(const ull*)&s_u[1][pxB];
        ull uB2 = *(const ull*)&s_u[2][pxB];
        ull uB3 = *(const ull*)&s_u[3][pxB];

        // software-pipelined channel loop
        ulonglong2 wA = s_w3d[cbase][0], wB = s_w3d[cbase][1];
        ull bb = s_b3d[cbase];
#pragma unroll
        for (int cc = 0; cc < 16; cc++) {
            int c = cbase + cc;
            ulonglong2 nwA, nwB; ull nbb;
            if (cc < 15) {
                nwA = s_w3d[c + 1][0]; nwB = s_w3d[c + 1][1]; nbb = s_b3d[c + 1];
            } else {
                nwA = wA; nwB = wB; nbb = bb;
            }
            ull zA = ffma2(uA0, wA.x, bb);
            zA = ffma2(uA1, wA.y, zA);
            zA = ffma2(uA2, wB.x, zA);
            zA = ffma2(uA3, wB.y, zA);
            accA[cc] = fadd2(accA[cc], relu2(zA));
            ull zB = ffma2(uB0, wA.x, bb);
            zB = ffma2(uB1, wA.y, zB);
            zB = ffma2(uB2, wB.x, zB);
            zB = ffma2(uB3, wB.y, zB);
            accB[cc] = fadd2(accB[cc], relu2(zB));
            wA = nwA; wB = nwB; bb = nbb;
        }
    }

#pragma unroll
    for (int cc = 0; cc < 16; cc++) {
        int c = cbase + cc;
        size_t base = (((size_t)n * 256 + c) * 64 + y) * 64;
        *(ull*)&out[base + pxA] = accA[cc];
        *(ull*)&out[base + pxB] = accB[cc];
    }
}

// ---------------------------------------------------------------------------
extern "C" void kernel_launch(void* const* d_in, const int* in_sizes, int n_in,
                              void* d_out, int out_size) {
    const float* x  = (const float*)d_in[0];
    const float* w1 = (const float*)d_in[1];
    const float* b1 = (const float*)d_in[2];
    const float* w2 = (const float*)d_in[3];
    const float* b2 = (const float*)d_in[4];
    const float* w3 = (const float*)d_in[5];
    const float* b3 = (const float*)d_in[6];
    float* out = (float*)d_out;

    k0_kernel<<<256, 256>>>(x, w1, b1);
    for (int i = 0; i < 32; i++)
        chain_kernel<<<256, 256>>>(w1, b1, w2, b2, w3, b3, i);
    acc_kernel<<<1024, 256>>>(w3, b3, out);
}

// round 10
// speedup vs baseline: 1.0221x; 1.0221x over previous
#include <cuda_runtime.h>

typedef unsigned long long ull;

// Chain state: 4-channel fields only. h1 ping-pong, h2 stored per block.
__device__ float g_h1[2][16][4][64][64];   //  2.1 MB
__device__ float g_h2[32][16][4][64][64];  // 33.6 MB

// ---- packed fp32x2 helpers --------------------------------------------------
__device__ __forceinline__ ull ffma2(ull a, ull b, ull c) {
    ull d; asm("fma.rn.f32x2 %0, %1, %2, %3;" : "=l"(d) : "l"(a), "l"(b), "l"(c)); return d;
}
__device__ __forceinline__ ull fadd2(ull a, ull b) {
    ull d; asm("add.rn.f32x2 %0, %1, %2;" : "=l"(d) : "l"(a), "l"(b)); return d;
}
__device__ __forceinline__ ull pack2(float lo, float hi) {
    ull d; asm("mov.b64 %0, {%1, %2};" : "=l"(d) : "f"(lo), "f"(hi)); return d;
}
__device__ __forceinline__ ull dup2(float v) { return pack2(v, v); }
__device__ __forceinline__ ull relu2(ull z) {
    float lo, hi; asm("mov.b64 {%0, %1}, %2;" : "=f"(lo), "=f"(hi) : "l"(z));
    return pack2(fmaxf(lo, 0.f), fmaxf(hi, 0.f));
}
__device__ __forceinline__ ull packmid(ull a, ull b) {
    float alo, ahi, blo, bhi;
    asm("mov.b64 {%0, %1}, %2;" : "=f"(alo), "=f"(ahi) : "l"(a));
    asm("mov.b64 {%0, %1}, %2;" : "=f"(blo), "=f"(bhi) : "l"(b));
    return pack2(ahi, blo);
}

// ---------------------------------------------------------------------------
// k0: h1_0 = relu(W1_0 @ x + b1_0).  Memory-bound (reads x, 67MB).
// ---------------------------------------------------------------------------
__global__ __launch_bounds__(256) void k0_kernel(const float* __restrict__ x,
                                                 const float* __restrict__ w1,
                                                 const float* __restrict__ b1) {
    __shared__ float4 sW1T[256];
    __shared__ float  sB1[4];
    int tid = threadIdx.x;
    if (tid < 4) sB1[tid] = b1[tid];
    sW1T[tid] = make_float4(w1[tid], w1[256 + tid], w1[512 + tid], w1[768 + tid]);
    __syncthreads();

    int n  = blockIdx.x >> 4;
    int yg = blockIdx.x & 15;
    int px = tid & 63;
    int y  = yg * 4 + (tid >> 6);

    const float* xp = x + (size_t)n * 256 * 4096 + y * 64 + px;
    float a0 = sB1[0], a1 = sB1[1], a2 = sB1[2], a3 = sB1[3];
#pragma unroll 8
    for (int c = 0; c < 256; c++) {
        float  xv = xp[c * 4096];
        float4 w  = sW1T[c];
        a0 = fmaf(xv, w.x, a0);
        a1 = fmaf(xv, w.y, a1);
        a2 = fmaf(xv, w.z, a2);
        a3 = fmaf(xv, w.w, a3);
    }
    float* hp = &g_h1[0][n][0][y][px];
    hp[0]     = fmaxf(a0, 0.f);
    hp[4096]  = fmaxf(a1, 0.f);
    hp[8192]  = fmaxf(a2, 0.f);
    hp[12288] = fmaxf(a3, 0.f);
}

// ---------------------------------------------------------------------------
// chain_kernel (block i): grid 128 (16 img x 8 tile-pairs), 1 CTA/SM wave,
// __launch_bounds__(256,1) -> up to 255 regs so ptxas can interleave.
// Each CTA: stage weights once, then process 2 tiles (16x16) sequentially.
// Fused loop: 2 channels x 2 pairs = 4 independent z-chains in flight.
// ---------------------------------------------------------------------------
__global__ __launch_bounds__(256, 1) void chain_kernel(
    const float* __restrict__ w1, const float* __restrict__ b1,
    const float* __restrict__ w2, const float* __restrict__ b2,
    const float* __restrict__ w3, const float* __restrict__ b3,
    int blk)
{
    __shared__ __align__(16) float s_h1[4][18][18];
    __shared__ ull        s_w2d[144];        // dup-packed [j][k][dy][dx]
    __shared__ float      s_b2[4];
    __shared__ ulonglong2 s_wall[256][4];    // [c]: {w3.xy, w3.zw, w1.01, w1.23} dup-packed
    __shared__ ulonglong2 s_b3p[128];        // [c/2]: {dup b3[2c], dup b3[2c+1]}
    __shared__ float      s_b1n[4];
    __shared__ ull        s_cp[4][4][128];   // conv partials [q][j][pair]
    __shared__ ull        s_part[3][4][128]; // fused partials [q-1][j][pair]

    int tid  = threadIdx.x;
    int dual = tid & 63;          // 0..63
    int q    = tid >> 6;          // 0..3
    int n    = blockIdx.x >> 3;
    int tpair = blockIdx.x & 7;   // tiles 2*tpair, 2*tpair+1

    int pA = dual;                // rows 0..7
    int pB = dual + 64;           // rows 8..15

    // ---- weight staging: ONCE per CTA (reused for both tiles) ----
    if (tid < 144) s_w2d[tid] = dup2(w2[blk * 144 + tid]);
    else if (tid < 148) s_b2[tid - 144] = b2[blk * 4 + (tid - 144)];
    if (blk < 31) {
        const float* w1n = w1 + (blk + 1) * 1024;
        int c = tid;
        float4 wr = *(const float4*)&w3[(blk * 256 + c) * 4];
        s_wall[c][0] = make_ulonglong2(dup2(wr.x), dup2(wr.y));
        s_wall[c][1] = make_ulonglong2(dup2(wr.z), dup2(wr.w));
        s_wall[c][2] = make_ulonglong2(dup2(w1n[c]),       dup2(w1n[256 + c]));
        s_wall[c][3] = make_ulonglong2(dup2(w1n[512 + c]), dup2(w1n[768 + c]));
        if ((c & 1) == 0)
            s_b3p[c >> 1] = make_ulonglong2(dup2(b3[blk * 256 + c]),
                                            dup2(b3[blk * 256 + c + 1]));
        if (tid >= 148 && tid < 152) s_b1n[tid - 148] = b1[(blk + 1) * 4 + (tid - 148)];
    }

    const float* h1base = &g_h1[blk & 1][n][0][0][0];

    for (int s2 = 0; s2 < 2; s2++) {
        int tile = tpair * 2 + s2;
        int ty0  = (tile >> 2) * 16;
        int tx0  = (tile & 3)  * 16;

        __syncthreads();   // staging done (s2=0) / prior tile's smem reads done (s2=1)

        // halo tile load: 18x18x4 (zero pad = SAME padding)
        for (int idx = tid; idx < 324; idx += 256) {
            int yy = idx / 18, xx = idx % 18;
            int gy = ty0 + yy - 1, gx = tx0 + xx - 1;
            bool ok = (gy >= 0 && gy < 64 && gx >= 0 && gx < 64);
#pragma unroll
            for (int k = 0; k < 4; k++)
                s_h1[k][yy][xx] = ok ? h1base[k * 4096 + gy * 64 + gx] : 0.f;
        }
        __syncthreads();

        // ---- conv3x3, input-channel k=q, for both pairs of this thread ----
#pragma unroll
        for (int s = 0; s < 2; s++) {
            int pair = s ? pB : pA;
            int py = pair >> 3;
            int x0 = (pair & 7) * 2;
            ull p0 = (q == 0) ? dup2(s_b2[0]) : 0ull;
            ull p1 = (q == 0) ? dup2(s_b2[1]) : 0ull;
            ull p2 = (q == 0) ? dup2(s_b2[2]) : 0ull;
            ull p3 = (q == 0) ? dup2(s_b2[3]) : 0ull;
#pragma unroll
            for (int dy = 0; dy < 3; dy++) {
                const ull* rowp = (const ull*)&s_h1[q][py + dy][x0];
                ull p01 = rowp[0], p23 = rowp[1];
                ull tap0 = p01, tap1 = packmid(p01, p23), tap2 = p23;
                int wi = q * 9 + dy * 3;
                p0 = ffma2(tap0, s_w2d[wi + 0], p0);
                p1 = ffma2(tap0, s_w2d[36 + wi + 0], p1);
                p2 = ffma2(tap0, s_w2d[72 + wi + 0], p2);
                p3 = ffma2(tap0, s_w2d[108 + wi + 0], p3);
                p0 = ffma2(tap1, s_w2d[wi + 1], p0);
                p1 = ffma2(tap1, s_w2d[36 + wi + 1], p1);
                p2 = ffma2(tap1, s_w2d[72 + wi + 1], p2);
                p3 = ffma2(tap1, s_w2d[108 + wi + 1], p3);
                p0 = ffma2(tap2, s_w2d[wi + 2], p0);
                p1 = ffma2(tap2, s_w2d[36 + wi + 2], p1);
                p2 = ffma2(tap2, s_w2d[72 + wi + 2], p2);
                p3 = ffma2(tap2, s_w2d[108 + wi + 2], p3);
            }
            s_cp[q][0][pair] = p0;
            s_cp[q][1][pair] = p1;
            s_cp[q][2][pair] = p2;
            s_cp[q][3][pair] = p3;
        }
        __syncthreads();

        ull uA0 = relu2(fadd2(fadd2(s_cp[0][0][pA], s_cp[1][0][pA]), fadd2(s_cp[2][0][pA], s_cp[3][0][pA])));
        ull uA1 = relu2(fadd2(fadd2(s_cp[0][1][pA], s_cp[1][1][pA]), fadd2(s_cp[2][1][pA], s_cp[3][1][pA])));
        ull uA2 = relu2(fadd2(fadd2(s_cp[0][2][pA], s_cp[1][2][pA]), fadd2(s_cp[2][2][pA], s_cp[3][2][pA])));
        ull uA3 = relu2(fadd2(fadd2(s_cp[0][3][pA], s_cp[1][3][pA]), fadd2(s_cp[2][3][pA], s_cp[3][3][pA])));
        ull uB0 = relu2(fadd2(fadd2(s_cp[0][0][pB], s_cp[1][0][pB]), fadd2(s_cp[2][0][pB], s_cp[3][0][pB])));
        ull uB1 = relu2(fadd2(fadd2(s_cp[0][1][pB], s_cp[1][1][pB]), fadd2(s_cp[2][1][pB], s_cp[3][1][pB])));
        ull uB2 = relu2(fadd2(fadd2(s_cp[0][2][pB], s_cp[1][2][pB]), fadd2(s_cp[2][2][pB], s_cp[3][2][pB])));
        ull uB3 = relu2(fadd2(fadd2(s_cp[0][3][pB], s_cp[1][3][pB]), fadd2(s_cp[2][3][pB], s_cp[3][3][pB])));

        int gyA = ty0 + (pA >> 3), gxA = tx0 + (pA & 7) * 2;
        int gyB = ty0 + (pB >> 3), gxB = tx0 + (pB & 7) * 2;
        if (q == 0) {
            ull* hA = (ull*)&g_h2[blk][n][0][gyA][gxA];
            hA[0] = uA0; hA[2048] = uA1; hA[4096] = uA2; hA[6144] = uA3;
            ull* hB = (ull*)&g_h2[blk][n][0][gyB][gxB];
            hB[0] = uB0; hB[2048] = uB1; hB[4096] = uB2; hB[6144] = uB3;
        }

        if (blk < 31) {
            ull aA0, aA1, aA2, aA3, aB0, aB1, aB2, aB3;
            if (q == 0) {
                aA0 = dup2(s_b1n[0]); aA1 = dup2(s_b1n[1]); aA2 = dup2(s_b1n[2]); aA3 = dup2(s_b1n[3]);
                aB0 = aA0; aB1 = aA1; aB2 = aA2; aB3 = aA3;
            } else {
                aA0 = aA1 = aA2 = aA3 = 0ull;
                aB0 = aB1 = aB2 = aB3 = 0ull;
            }
            int c0 = q << 6;

            // ---- fused loop: 2 channels x 2 pairs = 4 independent chains ----
#pragma unroll 2
            for (int cc = 0; cc < 64; cc += 2) {
                int c = c0 + cc;
                const ulonglong2* wp0 = s_wall[c];
                const ulonglong2* wp1 = s_wall[c + 1];
                ulonglong2 w0A = wp0[0], w0B = wp0[1];
                ulonglong2 w1A = wp1[0], w1B = wp1[1];
                ulonglong2 bbp = s_b3p[c >> 1];

                ull z0A = ffma2(uA0, w0A.x, bbp.x);
                ull z0B = ffma2(uB0, w0A.x, bbp.x);
                ull z1A = ffma2(uA0, w1A.x, bbp.y);
                ull z1B = ffma2(uB0, w1A.x, bbp.y);
                z0A = ffma2(uA1, w0A.y, z0A);
                z0B = ffma2(uB1, w0A.y, z0B);
                z1A = ffma2(uA1, w1A.y, z1A);
                z1B = ffma2(uB1, w1A.y, z1B);
                z0A = ffma2(uA2, w0B.x, z0A);
                z0B = ffma2(uB2, w0B.x, z0B);
                z1A = ffma2(uA2, w1B.x, z1A);
                z1B = ffma2(uB2, w1B.x, z1B);
                z0A = ffma2(uA3, w0B.y, z0A);
                z0B = ffma2(uB3, w0B.y, z0B);
                z1A = ffma2(uA3, w1B.y, z1A);
                z1B = ffma2(uB3, w1B.y, z1B);

                ull v0A = relu2(z0A);
                ull v0B = relu2(z0B);
                ull v1A = relu2(z1A);
                ull v1B = relu2(z1B);

                ulonglong2 q0A = wp0[2], q0B = wp0[3];
                ulonglong2 q1A = wp1[2], q1B = wp1[3];
                aA0 = ffma2(v0A, q0A.x, aA0);
                aB0 = ffma2(v0B, q0A.x, aB0);
                aA1 = ffma2(v0A, q0A.y, aA1);
                aB1 = ffma2(v0B, q0A.y, aB1);
                aA2 = ffma2(v0A, q0B.x, aA2);
                aB2 = ffma2(v0B, q0B.x, aB2);
                aA3 = ffma2(v0A, q0B.y, aA3);
                aB3 = ffma2(v0B, q0B.y, aB3);
                aA0 = ffma2(v1A, q1A.x, aA0);
                aB0 = ffma2(v1B, q1A.x, aB0);
                aA1 = ffma2(v1A, q1A.y, aA1);
                aB1 = ffma2(v1B, q1A.y, aB1);
                aA2 = ffma2(v1A, q1B.x, aA2);
                aB2 = ffma2(v1B, q1B.x, aB2);
                aA3 = ffma2(v1A, q1B.y, aA3);
                aB3 = ffma2(v1B, q1B.y, aB3);
            }

            if (q > 0) {
                s_part[q - 1][0][pA] = aA0; s_part[q - 1][1][pA] = aA1;
                s_part[q - 1][2][pA] = aA2; s_part[q - 1][3][pA] = aA3;
                s_part[q - 1][0][pB] = aB0; s_part[q - 1][1][pB] = aB1;
                s_part[q - 1][2][pB] = aB2; s_part[q - 1][3][pB] = aB3;
            }
            __syncthreads();
            if (q == 0) {
                aA0 = fadd2(fadd2(aA0, s_part[0][0][pA]), fadd2(s_part[1][0][pA], s_part[2][0][pA]));
                aA1 = fadd2(fadd2(aA1, s_part[0][1][pA]), fadd2(s_part[1][1][pA], s_part[2][1][pA]));
                aA2 = fadd2(fadd2(aA2, s_part[0][2][pA]), fadd2(s_part[1][2][pA], s_part[2][2][pA]));
                aA3 = fadd2(fadd2(aA3, s_part[0][3][pA]), fadd2(s_part[1][3][pA], s_part[2][3][pA]));
                ull* hp = (ull*)&g_h1[(blk + 1) & 1][n][0][gyA][gxA];
                hp[0]    = relu2(aA0);
                hp[2048] = relu2(aA1);
                hp[4096] = relu2(aA2);
                hp[6144] = relu2(aA3);
                aB0 = fadd2(fadd2(aB0, s_part[0][0][pB]), fadd2(s_part[1][0][pB], s_part[2][0][pB]));
                aB1 = fadd2(fadd2(aB1, s_part[0][1][pB]), fadd2(s_part[1][1][pB], s_part[2][1][pB]));
                aB2 = fadd2(fadd2(aB2, s_part[0][2][pB]), fadd2(s_part[1][2][pB], s_part[2][2][pB]));
                aB3 = fadd2(fadd2(aB3, s_part[0][3][pB]), fadd2(s_part[1][3][pB], s_part[2][3][pB]));
                ull* hq = (ull*)&g_h1[(blk + 1) & 1][n][0][gyB][gxB];
                hq[0]    = relu2(aB0);
                hq[2048] = relu2(aB1);
                hq[4096] = relu2(aB2);
                hq[6144] = relu2(aB3);
            }
        } else {
            __syncthreads();   // keep barrier count uniform across blk paths
        }
    }
}

// ---------------------------------------------------------------------------
// acc_kernel: out = sum_i relu(W3_i @ h2_i + b3_i)  (R8 form — at fma floor)
// Grid 1024 (16 img x 64 rows), 256 threads = 16 dual-slots x 16 ch-groups.
// ---------------------------------------------------------------------------
__global__ __launch_bounds__(256) void acc_kernel(const float* __restrict__ w3,
                                                  const float* __restrict__ b3,
                                                  float* __restrict__ out) {
    __shared__ ulonglong2 s_w3d[256][2];
    __shared__ ull        s_b3d[256];
    __shared__ __align__(16) float s_u[4][64];

    int tid   = threadIdx.x;
    int n     = blockIdx.x >> 6;
    int y     = blockIdx.x & 63;
    int dual  = tid & 15;
    int grp   = tid >> 4;
    int pxA   = dual * 2;
    int pxB   = pxA + 32;
    int cbase = grp * 16;

    ull accA[16], accB[16];
#pragma unroll
    for (int cc = 0; cc < 16; cc++) { accA[cc] = 0ull; accB[cc] = 0ull; }

    for (int i = 0; i < 32; i++) {
        __syncthreads();
        float4 wr = *(const float4*)&w3[(i * 256 + tid) * 4];
        s_w3d[tid][0] = make_ulonglong2(dup2(wr.x), dup2(wr.y));
        s_w3d[tid][1] = make_ulonglong2(dup2(wr.z), dup2(wr.w));
        s_b3d[tid]    = dup2(b3[i * 256 + tid]);
        s_u[tid >> 6][tid & 63] = g_h2[i][n][tid >> 6][y][tid & 63];
        __syncthreads();

        ull uA0 = *(const ull*)&s_u[0][pxA];
        ull uA1 = *(const ull*)&s_u[1][pxA];
        ull uA2 = *(const ull*)&s_u[2][pxA];
        ull uA3 = *(const ull*)&s_u[3][pxA];
        ull uB0 = *(const ull*)&s_u[0][pxB];
        ull uB1 = *(const ull*)&s_u[1][pxB];
        ull uB2 = *(const ull*)&s_u[2][pxB];
        ull uB3 = *(const ull*)&s_u[3][pxB];
#pragma unroll
        for (int cc = 0; cc < 16; cc++) {
            int c = cbase + cc;
            ulonglong2 wA = s_w3d[c][0], wB = s_w3d[c][1];
            ull bb = s_b3d[c];
            ull zA = ffma2(uA0, wA.x, bb);
            zA = ffma2(uA1, wA.y, zA);
            zA = ffma2(uA2, wB.x, zA);
            zA = ffma2(uA3, wB.y, zA);
            accA[cc] = fadd2(accA[cc], relu2(zA));
            ull zB = ffma2(uB0, wA.x, bb);
            zB = ffma2(uB1, wA.y, zB);
            zB = ffma2(uB2, wB.x, zB);
            zB = ffma2(uB3, wB.y, zB);
            accB[cc] = fadd2(accB[cc], relu2(zB));
        }
    }

#pragma unroll
    for (int cc = 0; cc < 16; cc++) {
        int c = cbase + cc;
        size_t base = (((size_t)n * 256 + c) * 64 + y) * 64;
        *(ull*)&out[base + pxA] = accA[cc];
        *(ull*)&out[base + pxB] = accB[cc];
    }
}

// ---------------------------------------------------------------------------
extern "C" void kernel_launch(void* const* d_in, const int* in_sizes, int n_in,
                              void* d_out, int out_size) {
    const float* x  = (const float*)d_in[0];
    const float* w1 = (const float*)d_in[1];
    const float* b1 = (const float*)d_in[2];
    const float* w2 = (const float*)d_in[3];
    const float* b2 = (const float*)d_in[4];
    const float* w3 = (const float*)d_in[5];
    const float* b3 = (const float*)d_in[6];
    float* out = (float*)d_out;

    k0_kernel<<<256, 256>>>(x, w1, b1);
    for (int i = 0; i < 32; i++)
        chain_kernel<<<128, 256>>>(w1, b1, w2, b2, w3, b3, i);
    acc_kernel<<<1024, 256>>>(w3, b3, out);
}